// round 2
// baseline (speedup 1.0000x reference)
#include <cuda_runtime.h>

#define NTOK   2048
#define DMODEL 256
#define NHEAD  8
#define NVIEW  4
#define DKH    32
#define EPSV   1e-6f
#define QKSCALE 0.17677669529663687f  /* 1/sqrt(32) */

// ---------------- scratch (no cudaMalloc allowed) ----------------
__device__ float g_Q[NTOK * DMODEL];
__device__ float g_K[NTOK * DMODEL];
__device__ float g_V[NTOK * DMODEL];
__device__ float g_O[NTOK * DMODEL];

// =================================================================
// Shared GEMM-NT body: C[2048,256] = A[2048,256] @ B[256,256]^T
// BM=BN=64, BK=16, 256 threads, 4x4 register tile per thread.
// =================================================================
__device__ __forceinline__ void gemm_nt_body(const float* __restrict__ A,
                                             const float* __restrict__ B,
                                             float* __restrict__ C)
{
    __shared__ float As[16][68];
    __shared__ float Bs[16][68];

    const int t  = threadIdx.x;
    const int tx = t & 15;
    const int ty = t >> 4;
    const int bi = blockIdx.y;   // row tile (2048/64 = 32)
    const int bj = blockIdx.x;   // col tile (256/64 = 4)

    const int row = t >> 2;        // 0..63
    const int k4  = (t & 3) * 4;   // 0,4,8,12

    const float* Ag = A + (size_t)(bi * 64 + row) * 256 + k4;
    const float* Bg = B + (size_t)(bj * 64 + row) * 256 + k4;

    float acc[4][4];
#pragma unroll
    for (int r = 0; r < 4; r++)
#pragma unroll
        for (int c = 0; c < 4; c++) acc[r][c] = 0.f;

    for (int k0 = 0; k0 < 256; k0 += 16) {
        float4 av = *reinterpret_cast<const float4*>(Ag + k0);
        float4 bv = *reinterpret_cast<const float4*>(Bg + k0);
        __syncthreads();
        As[k4 + 0][row] = av.x; As[k4 + 1][row] = av.y;
        As[k4 + 2][row] = av.z; As[k4 + 3][row] = av.w;
        Bs[k4 + 0][row] = bv.x; Bs[k4 + 1][row] = bv.y;
        Bs[k4 + 2][row] = bv.z; Bs[k4 + 3][row] = bv.w;
        __syncthreads();
#pragma unroll
        for (int kk = 0; kk < 16; kk++) {
            float4 a = *reinterpret_cast<const float4*>(&As[kk][ty * 4]);
            float4 b = *reinterpret_cast<const float4*>(&Bs[kk][tx * 4]);
            acc[0][0] = fmaf(a.x, b.x, acc[0][0]);
            acc[0][1] = fmaf(a.x, b.y, acc[0][1]);
            acc[0][2] = fmaf(a.x, b.z, acc[0][2]);
            acc[0][3] = fmaf(a.x, b.w, acc[0][3]);
            acc[1][0] = fmaf(a.y, b.x, acc[1][0]);
            acc[1][1] = fmaf(a.y, b.y, acc[1][1]);
            acc[1][2] = fmaf(a.y, b.z, acc[1][2]);
            acc[1][3] = fmaf(a.y, b.w, acc[1][3]);
            acc[2][0] = fmaf(a.z, b.x, acc[2][0]);
            acc[2][1] = fmaf(a.z, b.y, acc[2][1]);
            acc[2][2] = fmaf(a.z, b.z, acc[2][2]);
            acc[2][3] = fmaf(a.z, b.w, acc[2][3]);
            acc[3][0] = fmaf(a.w, b.x, acc[3][0]);
            acc[3][1] = fmaf(a.w, b.y, acc[3][1]);
            acc[3][2] = fmaf(a.w, b.z, acc[3][2]);
            acc[3][3] = fmaf(a.w, b.w, acc[3][3]);
        }
    }
#pragma unroll
    for (int r = 0; r < 4; r++) {
        float4 o = make_float4(acc[r][0], acc[r][1], acc[r][2], acc[r][3]);
        *reinterpret_cast<float4*>(C + (size_t)(bi * 64 + ty * 4 + r) * 256 + bj * 64 + tx * 4) = o;
    }
}

// One launch computes Q, K, V (gridDim.z selects weight + destination symbol).
__global__ __launch_bounds__(256) void gemm_qkv(const float* __restrict__ x,
                                                const float* __restrict__ Wq,
                                                const float* __restrict__ Wk,
                                                const float* __restrict__ Wv)
{
    const float* B = (blockIdx.z == 0) ? Wq : (blockIdx.z == 1) ? Wk : Wv;
    float*       C = (blockIdx.z == 0) ? g_Q : (blockIdx.z == 1) ? g_K : g_V;
    gemm_nt_body(x, B, C);
}

// Final projection: out = g_O @ Wo^T
__global__ __launch_bounds__(256) void gemm_out(const float* __restrict__ Wo,
                                                float* __restrict__ out)
{
    gemm_nt_body(g_O, Wo, out);
}

// =================================================================
// Fused attention:
//   p[h,i,j] = (eps + sum_m tau_h*pi[i,h,m]*adjs[m,i,j]) * exp(scale*Q_i.K_j)
//   O[i,h,:] = (sum_j p * V[j,h,:]) / (sum_j p)
// Grid: 128 blocks (i-tiles of 16). 256 threads. TJ = 32.
// =================================================================
#define TI 16
#define TJ 32
#define QS_STRIDE 260
#define WP_HSTRIDE 536   /* 16*33 rows + pad so 4 heads hit distinct banks */
#define WP_ISTRIDE 33

__global__ __launch_bounds__(256, 1) void attn_kernel(
    const float* __restrict__ pi,
    const float* __restrict__ tau,
    const float* __restrict__ adjs)
{
    extern __shared__ float sm[];
    float* Qs  = sm;                           // [16][260]
    float* Ks  = Qs + TI * QS_STRIDE;          // [32][260]
    float* Vs  = Ks + TJ * QS_STRIDE;          // [32][260]
    float* Wp  = Vs + TJ * QS_STRIDE;          // [8][536] : [h][i*33+j]
    float* pit = Wp + NHEAD * WP_HSTRIDE;      // [16][8][4] = tau*pi
    float* rs  = pit + TI * 32;                // [8][16]

    const int t  = threadIdx.x;
    const int i0 = blockIdx.x * TI;

    // ---- tau*pi into smem ----
    for (int idx = t; idx < TI * 32; idx += 256) {
        int hm = idx & 31;
        pit[idx] = tau[hm >> 2] * pi[(size_t)(i0 + (idx >> 5)) * 32 + hm];
    }
    // ---- Q tile into smem ----
#pragma unroll
    for (int r = 0; r < 4; r++) {
        int idx = t + r * 256;          // float4 units, 0..1023
        int i = idx >> 6, d4 = idx & 63;
        *reinterpret_cast<float4*>(Qs + i * QS_STRIDE + d4 * 4) =
            *reinterpret_cast<const float4*>(g_Q + (size_t)(i0 + i) * 256 + d4 * 4);
    }

    // QK-phase identity: warp = head
    const int warp = t >> 5;
    const int lane = t & 31;
    const int il = lane >> 3;   // 0..3  (i = il + 4*ii)
    const int jl = lane & 7;    // 0..7  (j = jl + 8*jj)

    // PV-phase identity
    const int ig = t >> 6;      // 0..3  (i = ig + 4*k)
    const int dg = t & 63;      // float4 column 0..63
    const int hv = dg >> 3;     // head owning this d range

    float acc[4][4];
#pragma unroll
    for (int k = 0; k < 4; k++)
#pragma unroll
        for (int c = 0; c < 4; c++) acc[k][c] = 0.f;
    float rsum[4] = {0.f, 0.f, 0.f, 0.f};

    __syncthreads();   // Qs, pit ready

    for (int j0 = 0; j0 < NTOK; j0 += TJ) {
        // ---- load K/V tiles ----
#pragma unroll
        for (int r = 0; r < 8; r++) {
            int idx = t + r * 256;       // 0..2047 float4 units
            int j = idx >> 6, d4 = idx & 63;
            *reinterpret_cast<float4*>(Ks + j * QS_STRIDE + d4 * 4) =
                *reinterpret_cast<const float4*>(g_K + (size_t)(j0 + j) * 256 + d4 * 4);
            *reinterpret_cast<float4*>(Vs + j * QS_STRIDE + d4 * 4) =
                *reinterpret_cast<const float4*>(g_V + (size_t)(j0 + j) * 256 + d4 * 4);
        }
        // ---- phase A: W[h,i,j] from global adjs ----
        {
            const int j = t & 31;       // lane
            const int ig2 = t >> 5;     // warp id -> i pair
#pragma unroll
            for (int ii = 0; ii < 2; ii++) {
                const int i = 2 * ig2 + ii;
                const size_t base = (size_t)(i0 + i) * NTOK + j0 + j;
                float a0 = adjs[0ul * NTOK * NTOK + base];
                float a1 = adjs[1ul * NTOK * NTOK + base];
                float a2 = adjs[2ul * NTOK * NTOK + base];
                float a3 = adjs[3ul * NTOK * NTOK + base];
                const float* pp = pit + i * 32;
#pragma unroll
                for (int h = 0; h < NHEAD; h++) {
                    float w = EPSV;
                    w = fmaf(pp[h * 4 + 0], a0, w);
                    w = fmaf(pp[h * 4 + 1], a1, w);
                    w = fmaf(pp[h * 4 + 2], a2, w);
                    w = fmaf(pp[h * 4 + 3], a3, w);
                    Wp[h * WP_HSTRIDE + i * WP_ISTRIDE + j] = w;
                }
            }
        }
        __syncthreads();

        // ---- phase B: QK^T, p = w*exp(scale*s), in-place into Wp ----
        {
            const float* qbase = Qs + warp * DKH;
            const float* kbase = Ks + warp * DKH;
            float s[4][4];
#pragma unroll
            for (int ii = 0; ii < 4; ii++)
#pragma unroll
                for (int jj = 0; jj < 4; jj++) s[ii][jj] = 0.f;

#pragma unroll
            for (int d4 = 0; d4 < 8; d4++) {
                float4 q[4], k[4];
#pragma unroll
                for (int ii = 0; ii < 4; ii++)
                    q[ii] = *reinterpret_cast<const float4*>(qbase + (il + 4 * ii) * QS_STRIDE + d4 * 4);
#pragma unroll
                for (int jj = 0; jj < 4; jj++)
                    k[jj] = *reinterpret_cast<const float4*>(kbase + (jl + 8 * jj) * QS_STRIDE + d4 * 4);
#pragma unroll
                for (int ii = 0; ii < 4; ii++)
#pragma unroll
                    for (int jj = 0; jj < 4; jj++) {
                        s[ii][jj] = fmaf(q[ii].x, k[jj].x, s[ii][jj]);
                        s[ii][jj] = fmaf(q[ii].y, k[jj].y, s[ii][jj]);
                        s[ii][jj] = fmaf(q[ii].z, k[jj].z, s[ii][jj]);
                        s[ii][jj] = fmaf(q[ii].w, k[jj].w, s[ii][jj]);
                    }
            }
            float* wph = Wp + warp * WP_HSTRIDE;
#pragma unroll
            for (int ii = 0; ii < 4; ii++) {
                const int i = il + 4 * ii;
#pragma unroll
                for (int jj = 0; jj < 4; jj++) {
                    const int j = jl + 8 * jj;
                    float w = wph[i * WP_ISTRIDE + j];
                    float p = w * __expf(s[ii][jj] * QKSCALE);
                    wph[i * WP_ISTRIDE + j] = p;
                    rsum[ii] += p;
                }
            }
        }
        __syncthreads();

        // ---- phase C: O += P * V ----
        {
            const float* ph = Wp + hv * WP_HSTRIDE;
            const float* vcol = Vs + dg * 4;
#pragma unroll 8
            for (int j = 0; j < TJ; j++) {
                float4 v = *reinterpret_cast<const float4*>(vcol + j * QS_STRIDE);
#pragma unroll
                for (int k = 0; k < 4; k++) {
                    float p = ph[(ig + 4 * k) * WP_ISTRIDE + j];
                    acc[k][0] = fmaf(p, v.x, acc[k][0]);
                    acc[k][1] = fmaf(p, v.y, acc[k][1]);
                    acc[k][2] = fmaf(p, v.z, acc[k][2]);
                    acc[k][3] = fmaf(p, v.w, acc[k][3]);
                }
            }
        }
        __syncthreads();   // protect Ks/Vs/Wp before next tile
    }

    // ---- rowsum reduce (QK mapping: lanes jl=0..7 share i) ----
#pragma unroll
    for (int ii = 0; ii < 4; ii++) {
        float v = rsum[ii];
        v += __shfl_xor_sync(0xffffffffu, v, 1);
        v += __shfl_xor_sync(0xffffffffu, v, 2);
        v += __shfl_xor_sync(0xffffffffu, v, 4);
        if (jl == 0) rs[warp * 16 + il + 4 * ii] = v;
    }
    __syncthreads();

    // ---- normalize + store (PV mapping) ----
#pragma unroll
    for (int k = 0; k < 4; k++) {
        const int i = ig + 4 * k;
        const float inv = 1.0f / rs[hv * 16 + i];
        float4 o = make_float4(acc[k][0] * inv, acc[k][1] * inv,
                               acc[k][2] * inv, acc[k][3] * inv);
        *reinterpret_cast<float4*>(g_O + (size_t)(i0 + i) * 256 + dg * 4) = o;
    }
}

// =================================================================
extern "C" void kernel_launch(void* const* d_in, const int* in_sizes, int n_in,
                              void* d_out, int out_size)
{
    const float* x    = (const float*)d_in[0];
    const float* pi   = (const float*)d_in[1];
    const float* tau  = (const float*)d_in[2];
    const float* adjs = (const float*)d_in[3];
    const float* Wq   = (const float*)d_in[4];
    const float* Wk   = (const float*)d_in[5];
    const float* Wv   = (const float*)d_in[6];
    const float* Wo   = (const float*)d_in[7];
    float* out = (float*)d_out;

    const int smem = (TI * QS_STRIDE + 2 * TJ * QS_STRIDE + NHEAD * WP_HSTRIDE +
                      TI * 32 + NHEAD * 16) * (int)sizeof(float);
    cudaFuncSetAttribute(attn_kernel, cudaFuncAttributeMaxDynamicSharedMemorySize, smem);

    gemm_qkv<<<dim3(4, 32, 3), 256>>>(x, Wq, Wk, Wv);
    attn_kernel<<<NTOK / TI, 256, smem>>>(pi, tau, adjs);
    gemm_out<<<dim3(4, 32), 256>>>(Wo, out);
}

// round 3
// speedup vs baseline: 1.1456x; 1.1456x over previous
#include <cuda_runtime.h>

#define NTOK   2048
#define NHEAD  8
#define EPSV   1e-6f
#define QKSCALE 0.17677669529663687f  /* 1/sqrt(32) */
#define NSPLIT 2
#define JHALF  (NTOK / NSPLIT)

// ---------------- scratch (no cudaMalloc allowed) ----------------
__device__ float g_Q[NTOK * 256];
__device__ float g_K[NTOK * 256];
__device__ float g_V[NTOK * 256];
__device__ float g_pn[NSPLIT * NTOK * 256];      // partial numerators
__device__ float g_pd[NSPLIT * NTOK * NHEAD];    // partial denominators

// ---------------- packed f32x2 helpers (FFMA2) ----------------
typedef unsigned long long ull;
__device__ __forceinline__ ull ffma2(ull a, ull b, ull c) {
    ull d;
    asm("fma.rn.f32x2 %0, %1, %2, %3;" : "=l"(d) : "l"(a), "l"(b), "l"(c));
    return d;
}
__device__ __forceinline__ ull pack2(float lo, float hi) {
    ull r;
    asm("mov.b64 %0, {%1, %2};" : "=l"(r) : "f"(lo), "f"(hi));
    return r;
}
__device__ __forceinline__ float2 unpack2(ull v) {
    float2 r;
    asm("mov.b64 {%0, %1}, %2;" : "=f"(r.x), "=f"(r.y) : "l"(v));
    return r;
}

// =================================================================
// GEMM (NT): C[2048,256] = A[2048,256] @ B[256,256]^T
// 2-stage double buffer, BK=16, f32x2 accumulation.
// COMBINE=true: A is materialized on the fly from partial num/den.
// =================================================================
template<bool COMBINE>
__device__ __forceinline__ void gemm_body(const float* __restrict__ A,
                                          const float* __restrict__ B,
                                          float* __restrict__ C)
{
    __shared__ __align__(16) float As[2][16][68];
    __shared__ __align__(16) float Bs[2][16][68];

    const int t  = threadIdx.x;
    const int tx = t & 15;
    const int ty = t >> 4;
    const int bi = blockIdx.y;   // row tile (2048/64 = 32)
    const int bj = blockIdx.x;   // col tile (256/64 = 4)

    const int row = t >> 2;        // 0..63
    const int k4  = (t & 3) * 4;   // 0,4,8,12
    const int arow = bi * 64 + row;
    const float* Bg = B + (size_t)(bj * 64 + row) * 256 + k4;

    float4 av, bv;

    // --- A fragment producer ---
    auto loadA = [&](int c0) -> float4 {
        if (COMBINE) {
            float4 n0 = *(const float4*)(g_pn + (size_t)arow * 256 + c0);
            float4 n1 = *(const float4*)(g_pn + (size_t)NTOK * 256 + (size_t)arow * 256 + c0);
            float den = g_pd[arow * NHEAD + (c0 >> 5)] +
                        g_pd[NTOK * NHEAD + arow * NHEAD + (c0 >> 5)];
            float inv = 1.0f / den;
            return make_float4((n0.x + n1.x) * inv, (n0.y + n1.y) * inv,
                               (n0.z + n1.z) * inv, (n0.w + n1.w) * inv);
        } else {
            return *(const float4*)(A + (size_t)arow * 256 + c0);
        }
    };

    // prologue: stage 0
    av = loadA(k4);
    bv = *(const float4*)(Bg);
    As[0][k4 + 0][row] = av.x; As[0][k4 + 1][row] = av.y;
    As[0][k4 + 2][row] = av.z; As[0][k4 + 3][row] = av.w;
    Bs[0][k4 + 0][row] = bv.x; Bs[0][k4 + 1][row] = bv.y;
    Bs[0][k4 + 2][row] = bv.z; Bs[0][k4 + 3][row] = bv.w;
    __syncthreads();

    ull acc2[4][2];
#pragma unroll
    for (int r = 0; r < 4; r++) { acc2[r][0] = 0ull; acc2[r][1] = 0ull; }

    for (int kt = 0; kt < 16; kt++) {
        const int cur = kt & 1;
        if (kt < 15) {
            av = loadA((kt + 1) * 16 + k4);
            bv = *(const float4*)(Bg + (kt + 1) * 16);
        }
#pragma unroll
        for (int kk = 0; kk < 16; kk++) {
            float4 a = *(const float4*)&As[cur][kk][ty * 4];
            ull b0 = *(const ull*)&Bs[cur][kk][tx * 4];
            ull b1 = *(const ull*)&Bs[cur][kk][tx * 4 + 2];
            ull a0 = pack2(a.x, a.x);
            acc2[0][0] = ffma2(a0, b0, acc2[0][0]);
            acc2[0][1] = ffma2(a0, b1, acc2[0][1]);
            ull a1 = pack2(a.y, a.y);
            acc2[1][0] = ffma2(a1, b0, acc2[1][0]);
            acc2[1][1] = ffma2(a1, b1, acc2[1][1]);
            ull a2 = pack2(a.z, a.z);
            acc2[2][0] = ffma2(a2, b0, acc2[2][0]);
            acc2[2][1] = ffma2(a2, b1, acc2[2][1]);
            ull a3 = pack2(a.w, a.w);
            acc2[3][0] = ffma2(a3, b0, acc2[3][0]);
            acc2[3][1] = ffma2(a3, b1, acc2[3][1]);
        }
        if (kt < 15) {
            const int nxt = cur ^ 1;
            As[nxt][k4 + 0][row] = av.x; As[nxt][k4 + 1][row] = av.y;
            As[nxt][k4 + 2][row] = av.z; As[nxt][k4 + 3][row] = av.w;
            Bs[nxt][k4 + 0][row] = bv.x; Bs[nxt][k4 + 1][row] = bv.y;
            Bs[nxt][k4 + 2][row] = bv.z; Bs[nxt][k4 + 3][row] = bv.w;
        }
        __syncthreads();
    }

#pragma unroll
    for (int r = 0; r < 4; r++) {
        float2 lo = unpack2(acc2[r][0]);
        float2 hi = unpack2(acc2[r][1]);
        *(float4*)(C + (size_t)(bi * 64 + ty * 4 + r) * 256 + bj * 64 + tx * 4) =
            make_float4(lo.x, lo.y, hi.x, hi.y);
    }
}

__global__ __launch_bounds__(256) void gemm_qkv(const float* __restrict__ x,
                                                const float* __restrict__ Wq,
                                                const float* __restrict__ Wk,
                                                const float* __restrict__ Wv)
{
    const float* B = (blockIdx.z == 0) ? Wq : (blockIdx.z == 1) ? Wk : Wv;
    float*       C = (blockIdx.z == 0) ? g_Q : (blockIdx.z == 1) ? g_K : g_V;
    gemm_body<false>(x, B, C);
}

__global__ __launch_bounds__(256) void gemm_out(const float* __restrict__ Wo,
                                                float* __restrict__ out)
{
    gemm_body<true>(nullptr, Wo, out);
}

// =================================================================
// Fused attention with j-split partials.
//   p[h,i,j] = (eps + sum_m tau_h*pi[i,h,m]*adjs[m,i,j]) * exp(scale*Q_i.K_j)
//   num[i,h,:] += p * V[j,h,:]    den[h,i] += p      (per split)
// Grid: (128 i-tiles of 16, 2 j-splits). 256 threads. TJ=32.
// Warp == head for phases A-index/B/C; Wp is warp-private between B and C.
// =================================================================
#define TI 16
#define TJ 32
#define KV_STRIDE 260
#define QT_STRIDE 18
#define WP_H 536
#define WP_I 33
// smem float offsets
#define OFF_QT  0            /* [256][18]  = 4608 */
#define OFF_KS  4608         /* [32][260]  = 8320 */
#define OFF_VS  12928        /* [32][260]  = 8320 */
#define OFF_WP  21248        /* [8][536]   = 4288 */
#define OFF_PIT 25536        /* [16][32]   = 512  */
#define SMEM_FLOATS 26048

__global__ __launch_bounds__(256, 2) void attn_kernel(
    const float* __restrict__ pi,
    const float* __restrict__ tau,
    const float* __restrict__ adjs)
{
    extern __shared__ float sm[];
    float* Qt  = sm + OFF_QT;
    float* Ks  = sm + OFF_KS;
    float* Vs  = sm + OFF_VS;
    float* Wp  = sm + OFF_WP;
    float* pit = sm + OFF_PIT;

    const int t    = threadIdx.x;
    const int warp = t >> 5;          // head
    const int lane = t & 31;
    const int i0   = blockIdx.x * TI;
    const int split = blockIdx.y;
    const int jbase = split * JHALF;

    // ---- prologue: tau*pi ----
    for (int idx = t; idx < TI * 32; idx += 256) {
        int hm = idx & 31;
        pit[idx] = tau[hm >> 2] * pi[(size_t)(i0 + (idx >> 5)) * 32 + hm];
    }
    // ---- prologue: transposed Q tile Qt[d][i] (once per block) ----
#pragma unroll
    for (int r = 0; r < 4; r++) {
        int idx = t + r * 256;
        int i = idx >> 6, d4 = idx & 63;
        float4 q = *(const float4*)(g_Q + (size_t)(i0 + i) * 256 + d4 * 4);
        Qt[(d4 * 4 + 0) * QT_STRIDE + i] = q.x;
        Qt[(d4 * 4 + 1) * QT_STRIDE + i] = q.y;
        Qt[(d4 * 4 + 2) * QT_STRIDE + i] = q.z;
        Qt[(d4 * 4 + 3) * QT_STRIDE + i] = q.w;
    }
    __syncthreads();

    const int il = lane >> 3;   // 0..3 (i-pair group, phase B)
    const int jl = lane & 7;    // 0..7 (j group, phase B)
    const int iw = lane >> 3;   // 0..3 (i group, phase C)
    const int dl = lane & 7;    // 0..7 (d4 col, phase C)
    const int hb = warp * 32;   // head column base
    float* wph = Wp + warp * WP_H;

    ull acc2[4][2];
#pragma unroll
    for (int k = 0; k < 4; k++) { acc2[k][0] = 0ull; acc2[k][1] = 0ull; }
    float rsum[4] = {0.f, 0.f, 0.f, 0.f};   // rows 2*(il+4*ii)+par

    for (int jt = 0; jt < JHALF / TJ; jt++) {
        const int j0 = jbase + jt * TJ;

        // ---- K/V tiles into smem ----
#pragma unroll
        for (int r = 0; r < 8; r++) {
            int idx = t + r * 256;
            int j = idx >> 6, d4 = idx & 63;
            *(float4*)(Ks + j * KV_STRIDE + d4 * 4) =
                *(const float4*)(g_K + (size_t)(j0 + j) * 256 + d4 * 4);
            *(float4*)(Vs + j * KV_STRIDE + d4 * 4) =
                *(const float4*)(g_V + (size_t)(j0 + j) * 256 + d4 * 4);
        }

        // ---- phase A: W[h,i,j] from global adjs (warp -> 2 i-rows) ----
        {
            const int j = lane;
#pragma unroll
            for (int ii = 0; ii < 2; ii++) {
                const int i = 2 * warp + ii;
                const size_t base = (size_t)(i0 + i) * NTOK + j0 + j;
                float a0 = adjs[base];
                float a1 = adjs[(size_t)NTOK * NTOK + base];
                float a2 = adjs[2ull * NTOK * NTOK + base];
                float a3 = adjs[3ull * NTOK * NTOK + base];
                const float* pp = pit + i * 32;
#pragma unroll
                for (int h = 0; h < NHEAD; h++) {
                    float w = EPSV;
                    w = fmaf(pp[h * 4 + 0], a0, w);
                    w = fmaf(pp[h * 4 + 1], a1, w);
                    w = fmaf(pp[h * 4 + 2], a2, w);
                    w = fmaf(pp[h * 4 + 3], a3, w);
                    Wp[h * WP_H + i * WP_I + j] = w;
                }
            }
        }
        __syncthreads();

        // ---- phase B: QK^T (i-paired FFMA2), p = w*exp(scale*s) ----
        {
            ull s2[2][4];
#pragma unroll
            for (int ii = 0; ii < 2; ii++)
#pragma unroll
                for (int jj = 0; jj < 4; jj++) s2[ii][jj] = 0ull;

#pragma unroll
            for (int d4 = 0; d4 < 8; d4++) {
                float kv[4][4];
#pragma unroll
                for (int jj = 0; jj < 4; jj++) {
                    float4 kq = *(const float4*)(Ks + (jl + 8 * jj) * KV_STRIDE + hb + d4 * 4);
                    kv[jj][0] = kq.x; kv[jj][1] = kq.y;
                    kv[jj][2] = kq.z; kv[jj][3] = kq.w;
                }
#pragma unroll
                for (int c = 0; c < 4; c++) {
                    const int dcol = hb + d4 * 4 + c;
                    ull q0 = *(const ull*)(Qt + dcol * QT_STRIDE + 2 * il);
                    ull q1 = *(const ull*)(Qt + dcol * QT_STRIDE + 2 * il + 8);
#pragma unroll
                    for (int jj = 0; jj < 4; jj++) {
                        ull kk2 = pack2(kv[jj][c], kv[jj][c]);
                        s2[0][jj] = ffma2(q0, kk2, s2[0][jj]);
                        s2[1][jj] = ffma2(q1, kk2, s2[1][jj]);
                    }
                }
            }
#pragma unroll
            for (int ii = 0; ii < 2; ii++) {
                const int r0 = 2 * (il + 4 * ii);
#pragma unroll
                for (int jj = 0; jj < 4; jj++) {
                    float2 s = unpack2(s2[ii][jj]);
                    const int j = jl + 8 * jj;
                    float w0 = wph[r0 * WP_I + j];
                    float w1 = wph[(r0 + 1) * WP_I + j];
                    float p0 = w0 * __expf(s.x * QKSCALE);
                    float p1 = w1 * __expf(s.y * QKSCALE);
                    wph[r0 * WP_I + j] = p0;
                    wph[(r0 + 1) * WP_I + j] = p1;
                    rsum[ii * 2 + 0] += p0;
                    rsum[ii * 2 + 1] += p1;
                }
            }
        }
        __syncwarp();   // Wp is warp-private: B stores -> C loads

        // ---- phase C: num += P * V (d-paired FFMA2) ----
        {
#pragma unroll 8
            for (int j = 0; j < TJ; j++) {
                ull va = *(const ull*)(Vs + j * KV_STRIDE + hb + dl * 4);
                ull vb = *(const ull*)(Vs + j * KV_STRIDE + hb + dl * 4 + 2);
#pragma unroll
                for (int k = 0; k < 4; k++) {
                    float p = wph[(iw + 4 * k) * WP_I + j];
                    ull pp2 = pack2(p, p);
                    acc2[k][0] = ffma2(pp2, va, acc2[k][0]);
                    acc2[k][1] = ffma2(pp2, vb, acc2[k][1]);
                }
            }
        }
        __syncthreads();   // protect Ks/Vs/Wp before next tile
    }

    // ---- denominators: reduce over jl lanes, store partials ----
#pragma unroll
    for (int v = 0; v < 4; v++) {
        float x = rsum[v];
        x += __shfl_xor_sync(0xffffffffu, x, 1);
        x += __shfl_xor_sync(0xffffffffu, x, 2);
        x += __shfl_xor_sync(0xffffffffu, x, 4);
        rsum[v] = x;
    }
    if (jl == 0) {
#pragma unroll
        for (int ii = 0; ii < 2; ii++)
#pragma unroll
            for (int par = 0; par < 2; par++) {
                int rrow = 2 * (il + 4 * ii) + par;
                g_pd[(size_t)split * NTOK * NHEAD + (size_t)(i0 + rrow) * NHEAD + warp] =
                    rsum[ii * 2 + par];
            }
    }
    // ---- numerators ----
#pragma unroll
    for (int k = 0; k < 4; k++) {
        int i = iw + 4 * k;
        float2 a = unpack2(acc2[k][0]);
        float2 b = unpack2(acc2[k][1]);
        *(float4*)(g_pn + (size_t)split * NTOK * 256 + (size_t)(i0 + i) * 256 + hb + dl * 4) =
            make_float4(a.x, a.y, b.x, b.y);
    }
}

// =================================================================
extern "C" void kernel_launch(void* const* d_in, const int* in_sizes, int n_in,
                              void* d_out, int out_size)
{
    const float* x    = (const float*)d_in[0];
    const float* pi   = (const float*)d_in[1];
    const float* tau  = (const float*)d_in[2];
    const float* adjs = (const float*)d_in[3];
    const float* Wq   = (const float*)d_in[4];
    const float* Wk   = (const float*)d_in[5];
    const float* Wv   = (const float*)d_in[6];
    const float* Wo   = (const float*)d_in[7];
    float* out = (float*)d_out;

    const int smem = SMEM_FLOATS * (int)sizeof(float);
    cudaFuncSetAttribute(attn_kernel, cudaFuncAttributeMaxDynamicSharedMemorySize, smem);

    gemm_qkv<<<dim3(4, 32, 3), 256>>>(x, Wq, Wk, Wv);
    attn_kernel<<<dim3(NTOK / TI, NSPLIT), 256, smem>>>(pi, tau, adjs);
    gemm_out<<<dim3(4, 32), 256>>>(Wo, out);
}

// round 4
// speedup vs baseline: 1.1457x; 1.0001x over previous
#include <cuda_runtime.h>

#define NTOK   2048
#define NHEAD  8
#define EPSV   1e-6f
#define QKSCALE 0.17677669529663687f  /* 1/sqrt(32) */
#define NSPLIT 2
#define JHALF  (NTOK / NSPLIT)

// ---------------- scratch (no cudaMalloc allowed) ----------------
__device__ float g_Q[NTOK * 256];
__device__ float g_K[NTOK * 256];
__device__ float g_V[NTOK * 256];
__device__ float g_pn[NSPLIT * NTOK * 256];      // partial numerators
__device__ float g_pd[NSPLIT * NTOK * NHEAD];    // partial denominators

// ---------------- packed f32x2 helpers (FFMA2) ----------------
typedef unsigned long long ull;
__device__ __forceinline__ ull ffma2(ull a, ull b, ull c) {
    ull d;
    asm("fma.rn.f32x2 %0, %1, %2, %3;" : "=l"(d) : "l"(a), "l"(b), "l"(c));
    return d;
}
__device__ __forceinline__ ull pack2(float lo, float hi) {
    ull r;
    asm("mov.b64 %0, {%1, %2};" : "=l"(r) : "f"(lo), "f"(hi));
    return r;
}
__device__ __forceinline__ float2 unpack2(ull v) {
    float2 r;
    asm("mov.b64 {%0, %1}, %2;" : "=f"(r.x), "=f"(r.y) : "l"(v));
    return r;
}

// =================================================================
// GEMM (NT): C[2048,256] = A[2048,256] @ B[256,256]^T
// 2-stage double buffer, BK=16, f32x2 accumulation.
// COMBINE=true: A is materialized on the fly from partial num/den.
// =================================================================
template<bool COMBINE>
__device__ __forceinline__ void gemm_body(const float* __restrict__ A,
                                          const float* __restrict__ B,
                                          float* __restrict__ C)
{
    __shared__ __align__(16) float As[2][16][68];
    __shared__ __align__(16) float Bs[2][16][68];

    const int t  = threadIdx.x;
    const int tx = t & 15;
    const int ty = t >> 4;
    const int bi = blockIdx.y;   // row tile (2048/64 = 32)
    const int bj = blockIdx.x;   // col tile (256/64 = 4)

    const int row = t >> 2;        // 0..63
    const int k4  = (t & 3) * 4;   // 0,4,8,12
    const int arow = bi * 64 + row;
    const float* Bg = B + (size_t)(bj * 64 + row) * 256 + k4;

    float4 av, bv;

    // --- A fragment producer ---
    auto loadA = [&](int c0) -> float4 {
        if (COMBINE) {
            float4 n0 = *(const float4*)(g_pn + (size_t)arow * 256 + c0);
            float4 n1 = *(const float4*)(g_pn + (size_t)NTOK * 256 + (size_t)arow * 256 + c0);
            float den = g_pd[arow * NHEAD + (c0 >> 5)] +
                        g_pd[NTOK * NHEAD + arow * NHEAD + (c0 >> 5)];
            float inv = 1.0f / den;
            return make_float4((n0.x + n1.x) * inv, (n0.y + n1.y) * inv,
                               (n0.z + n1.z) * inv, (n0.w + n1.w) * inv);
        } else {
            return *(const float4*)(A + (size_t)arow * 256 + c0);
        }
    };

    // prologue: stage 0
    av = loadA(k4);
    bv = *(const float4*)(Bg);
    As[0][k4 + 0][row] = av.x; As[0][k4 + 1][row] = av.y;
    As[0][k4 + 2][row] = av.z; As[0][k4 + 3][row] = av.w;
    Bs[0][k4 + 0][row] = bv.x; Bs[0][k4 + 1][row] = bv.y;
    Bs[0][k4 + 2][row] = bv.z; Bs[0][k4 + 3][row] = bv.w;
    __syncthreads();

    ull acc2[4][2];
#pragma unroll
    for (int r = 0; r < 4; r++) { acc2[r][0] = 0ull; acc2[r][1] = 0ull; }

    for (int kt = 0; kt < 16; kt++) {
        const int cur = kt & 1;
        if (kt < 15) {
            av = loadA((kt + 1) * 16 + k4);
            bv = *(const float4*)(Bg + (kt + 1) * 16);
        }
#pragma unroll
        for (int kk = 0; kk < 16; kk++) {
            float4 a = *(const float4*)&As[cur][kk][ty * 4];
            ull b0 = *(const ull*)&Bs[cur][kk][tx * 4];
            ull b1 = *(const ull*)&Bs[cur][kk][tx * 4 + 2];
            ull a0 = pack2(a.x, a.x);
            acc2[0][0] = ffma2(a0, b0, acc2[0][0]);
            acc2[0][1] = ffma2(a0, b1, acc2[0][1]);
            ull a1 = pack2(a.y, a.y);
            acc2[1][0] = ffma2(a1, b0, acc2[1][0]);
            acc2[1][1] = ffma2(a1, b1, acc2[1][1]);
            ull a2 = pack2(a.z, a.z);
            acc2[2][0] = ffma2(a2, b0, acc2[2][0]);
            acc2[2][1] = ffma2(a2, b1, acc2[2][1]);
            ull a3 = pack2(a.w, a.w);
            acc2[3][0] = ffma2(a3, b0, acc2[3][0]);
            acc2[3][1] = ffma2(a3, b1, acc2[3][1]);
        }
        if (kt < 15) {
            const int nxt = cur ^ 1;
            As[nxt][k4 + 0][row] = av.x; As[nxt][k4 + 1][row] = av.y;
            As[nxt][k4 + 2][row] = av.z; As[nxt][k4 + 3][row] = av.w;
            Bs[nxt][k4 + 0][row] = bv.x; Bs[nxt][k4 + 1][row] = bv.y;
            Bs[nxt][k4 + 2][row] = bv.z; Bs[nxt][k4 + 3][row] = bv.w;
        }
        __syncthreads();
    }

#pragma unroll
    for (int r = 0; r < 4; r++) {
        float2 lo = unpack2(acc2[r][0]);
        float2 hi = unpack2(acc2[r][1]);
        *(float4*)(C + (size_t)(bi * 64 + ty * 4 + r) * 256 + bj * 64 + tx * 4) =
            make_float4(lo.x, lo.y, hi.x, hi.y);
    }
}

__global__ __launch_bounds__(256) void gemm_qkv(const float* __restrict__ x,
                                                const float* __restrict__ Wq,
                                                const float* __restrict__ Wk,
                                                const float* __restrict__ Wv)
{
    const float* B = (blockIdx.z == 0) ? Wq : (blockIdx.z == 1) ? Wk : Wv;
    float*       C = (blockIdx.z == 0) ? g_Q : (blockIdx.z == 1) ? g_K : g_V;
    gemm_body<false>(x, B, C);
}

__global__ __launch_bounds__(256) void gemm_out(const float* __restrict__ Wo,
                                                float* __restrict__ out)
{
    gemm_body<true>(nullptr, Wo, out);
}

// =================================================================
// Fused attention with j-split partials.
//   p[h,i,j] = (eps + sum_m tau_h*pi[i,h,m]*adjs[m,i,j]) * exp(scale*Q_i.K_j)
//   num[i,h,:] += p * V[j,h,:]    den[h,i] += p      (per split)
// Grid: (128 i-tiles of 16, 2 j-splits). 256 threads. TJ=32.
// Warp == head for phases A-index/B/C; Wp is warp-private between B and C.
// =================================================================
#define TI 16
#define TJ 32
#define KV_STRIDE 260
#define QT_STRIDE 18
#define WP_H 536
#define WP_I 33
// smem float offsets
#define OFF_QT  0            /* [256][18]  = 4608 */
#define OFF_KS  4608         /* [32][260]  = 8320 */
#define OFF_VS  12928        /* [32][260]  = 8320 */
#define OFF_WP  21248        /* [8][536]   = 4288 */
#define OFF_PIT 25536        /* [16][32]   = 512  */
#define SMEM_FLOATS 26048

__global__ __launch_bounds__(256, 2) void attn_kernel(
    const float* __restrict__ pi,
    const float* __restrict__ tau,
    const float* __restrict__ adjs)
{
    extern __shared__ float sm[];
    float* Qt  = sm + OFF_QT;
    float* Ks  = sm + OFF_KS;
    float* Vs  = sm + OFF_VS;
    float* Wp  = sm + OFF_WP;
    float* pit = sm + OFF_PIT;

    const int t    = threadIdx.x;
    const int warp = t >> 5;          // head
    const int lane = t & 31;
    const int i0   = blockIdx.x * TI;
    const int split = blockIdx.y;
    const int jbase = split * JHALF;

    // ---- prologue: tau*pi ----
    for (int idx = t; idx < TI * 32; idx += 256) {
        int hm = idx & 31;
        pit[idx] = tau[hm >> 2] * pi[(size_t)(i0 + (idx >> 5)) * 32 + hm];
    }
    // ---- prologue: transposed Q tile Qt[d][i] (once per block) ----
#pragma unroll
    for (int r = 0; r < 4; r++) {
        int idx = t + r * 256;
        int i = idx >> 6, d4 = idx & 63;
        float4 q = *(const float4*)(g_Q + (size_t)(i0 + i) * 256 + d4 * 4);
        Qt[(d4 * 4 + 0) * QT_STRIDE + i] = q.x;
        Qt[(d4 * 4 + 1) * QT_STRIDE + i] = q.y;
        Qt[(d4 * 4 + 2) * QT_STRIDE + i] = q.z;
        Qt[(d4 * 4 + 3) * QT_STRIDE + i] = q.w;
    }
    __syncthreads();

    const int il = lane >> 3;   // 0..3 (i-pair group, phase B)
    const int jl = lane & 7;    // 0..7 (j group, phase B)
    const int iw = lane >> 3;   // 0..3 (i group, phase C)
    const int dl = lane & 7;    // 0..7 (d4 col, phase C)
    const int hb = warp * 32;   // head column base
    float* wph = Wp + warp * WP_H;

    ull acc2[4][2];
#pragma unroll
    for (int k = 0; k < 4; k++) { acc2[k][0] = 0ull; acc2[k][1] = 0ull; }
    float rsum[4] = {0.f, 0.f, 0.f, 0.f};   // rows 2*(il+4*ii)+par

    for (int jt = 0; jt < JHALF / TJ; jt++) {
        const int j0 = jbase + jt * TJ;

        // ---- K/V tiles into smem ----
#pragma unroll
        for (int r = 0; r < 8; r++) {
            int idx = t + r * 256;
            int j = idx >> 6, d4 = idx & 63;
            *(float4*)(Ks + j * KV_STRIDE + d4 * 4) =
                *(const float4*)(g_K + (size_t)(j0 + j) * 256 + d4 * 4);
            *(float4*)(Vs + j * KV_STRIDE + d4 * 4) =
                *(const float4*)(g_V + (size_t)(j0 + j) * 256 + d4 * 4);
        }

        // ---- phase A: W[h,i,j] from global adjs (warp -> 2 i-rows) ----
        {
            const int j = lane;
#pragma unroll
            for (int ii = 0; ii < 2; ii++) {
                const int i = 2 * warp + ii;
                const size_t base = (size_t)(i0 + i) * NTOK + j0 + j;
                float a0 = adjs[base];
                float a1 = adjs[(size_t)NTOK * NTOK + base];
                float a2 = adjs[2ull * NTOK * NTOK + base];
                float a3 = adjs[3ull * NTOK * NTOK + base];
                const float* pp = pit + i * 32;
#pragma unroll
                for (int h = 0; h < NHEAD; h++) {
                    float w = EPSV;
                    w = fmaf(pp[h * 4 + 0], a0, w);
                    w = fmaf(pp[h * 4 + 1], a1, w);
                    w = fmaf(pp[h * 4 + 2], a2, w);
                    w = fmaf(pp[h * 4 + 3], a3, w);
                    Wp[h * WP_H + i * WP_I + j] = w;
                }
            }
        }
        __syncthreads();

        // ---- phase B: QK^T (i-paired FFMA2), p = w*exp(scale*s) ----
        {
            ull s2[2][4];
#pragma unroll
            for (int ii = 0; ii < 2; ii++)
#pragma unroll
                for (int jj = 0; jj < 4; jj++) s2[ii][jj] = 0ull;

#pragma unroll
            for (int d4 = 0; d4 < 8; d4++) {
                float kv[4][4];
#pragma unroll
                for (int jj = 0; jj < 4; jj++) {
                    float4 kq = *(const float4*)(Ks + (jl + 8 * jj) * KV_STRIDE + hb + d4 * 4);
                    kv[jj][0] = kq.x; kv[jj][1] = kq.y;
                    kv[jj][2] = kq.z; kv[jj][3] = kq.w;
                }
#pragma unroll
                for (int c = 0; c < 4; c++) {
                    const int dcol = hb + d4 * 4 + c;
                    ull q0 = *(const ull*)(Qt + dcol * QT_STRIDE + 2 * il);
                    ull q1 = *(const ull*)(Qt + dcol * QT_STRIDE + 2 * il + 8);
#pragma unroll
                    for (int jj = 0; jj < 4; jj++) {
                        ull kk2 = pack2(kv[jj][c], kv[jj][c]);
                        s2[0][jj] = ffma2(q0, kk2, s2[0][jj]);
                        s2[1][jj] = ffma2(q1, kk2, s2[1][jj]);
                    }
                }
            }
#pragma unroll
            for (int ii = 0; ii < 2; ii++) {
                const int r0 = 2 * (il + 4 * ii);
#pragma unroll
                for (int jj = 0; jj < 4; jj++) {
                    float2 s = unpack2(s2[ii][jj]);
                    const int j = jl + 8 * jj;
                    float w0 = wph[r0 * WP_I + j];
                    float w1 = wph[(r0 + 1) * WP_I + j];
                    float p0 = w0 * __expf(s.x * QKSCALE);
                    float p1 = w1 * __expf(s.y * QKSCALE);
                    wph[r0 * WP_I + j] = p0;
                    wph[(r0 + 1) * WP_I + j] = p1;
                    rsum[ii * 2 + 0] += p0;
                    rsum[ii * 2 + 1] += p1;
                }
            }
        }
        __syncwarp();   // Wp is warp-private: B stores -> C loads

        // ---- phase C: num += P * V (d-paired FFMA2) ----
        {
#pragma unroll 8
            for (int j = 0; j < TJ; j++) {
                ull va = *(const ull*)(Vs + j * KV_STRIDE + hb + dl * 4);
                ull vb = *(const ull*)(Vs + j * KV_STRIDE + hb + dl * 4 + 2);
#pragma unroll
                for (int k = 0; k < 4; k++) {
                    float p = wph[(iw + 4 * k) * WP_I + j];
                    ull pp2 = pack2(p, p);
                    acc2[k][0] = ffma2(pp2, va, acc2[k][0]);
                    acc2[k][1] = ffma2(pp2, vb, acc2[k][1]);
                }
            }
        }
        __syncthreads();   // protect Ks/Vs/Wp before next tile
    }

    // ---- denominators: reduce over jl lanes, store partials ----
#pragma unroll
    for (int v = 0; v < 4; v++) {
        float x = rsum[v];
        x += __shfl_xor_sync(0xffffffffu, x, 1);
        x += __shfl_xor_sync(0xffffffffu, x, 2);
        x += __shfl_xor_sync(0xffffffffu, x, 4);
        rsum[v] = x;
    }
    if (jl == 0) {
#pragma unroll
        for (int ii = 0; ii < 2; ii++)
#pragma unroll
            for (int par = 0; par < 2; par++) {
                int rrow = 2 * (il + 4 * ii) + par;
                g_pd[(size_t)split * NTOK * NHEAD + (size_t)(i0 + rrow) * NHEAD + warp] =
                    rsum[ii * 2 + par];
            }
    }
    // ---- numerators ----
#pragma unroll
    for (int k = 0; k < 4; k++) {
        int i = iw + 4 * k;
        float2 a = unpack2(acc2[k][0]);
        float2 b = unpack2(acc2[k][1]);
        *(float4*)(g_pn + (size_t)split * NTOK * 256 + (size_t)(i0 + i) * 256 + hb + dl * 4) =
            make_float4(a.x, a.y, b.x, b.y);
    }
}

// =================================================================
extern "C" void kernel_launch(void* const* d_in, const int* in_sizes, int n_in,
                              void* d_out, int out_size)
{
    const float* x    = (const float*)d_in[0];
    const float* pi   = (const float*)d_in[1];
    const float* tau  = (const float*)d_in[2];
    const float* adjs = (const float*)d_in[3];
    const float* Wq   = (const float*)d_in[4];
    const float* Wk   = (const float*)d_in[5];
    const float* Wv   = (const float*)d_in[6];
    const float* Wo   = (const float*)d_in[7];
    float* out = (float*)d_out;

    const int smem = SMEM_FLOATS * (int)sizeof(float);
    cudaFuncSetAttribute(attn_kernel, cudaFuncAttributeMaxDynamicSharedMemorySize, smem);

    gemm_qkv<<<dim3(4, 32, 3), 256>>>(x, Wq, Wk, Wv);
    attn_kernel<<<dim3(NTOK / TI, NSPLIT), 256, smem>>>(pi, tau, adjs);
    gemm_out<<<dim3(4, 32), 256>>>(Wo, out);
}

// round 6
// speedup vs baseline: 2.0555x; 1.7940x over previous
#include <cuda_runtime.h>
#include <cuda_bf16.h>
#include <cstdint>

#define NTOK 2048
#define NHEAD 8
#define EPSV 1e-6f
#define QKSCALE 0.17677669529663687f
#define NSPL 4
#define JR (NTOK / NSPL)      /* 512 per split */
#define TIA 32
#define TJA 32
#define NJT (JR / TJA)        /* 16 tiles */
#define KSTR 264              /* bf16 elems per smem row (528 B) */

typedef unsigned long long ull;

__device__ float g_Q[NTOK * 256];
__device__ float g_K[NTOK * 256];
__device__ float g_V[NTOK * 256];
__device__ float g_pn[NSPL * NTOK * 256];
__device__ float g_pd[NSPL * NTOK * NHEAD];

/* ---------------- f32x2 helpers (projection GEMMs) ---------------- */
__device__ __forceinline__ ull ffma2(ull a, ull b, ull c) {
    ull d; asm("fma.rn.f32x2 %0, %1, %2, %3;" : "=l"(d) : "l"(a), "l"(b), "l"(c)); return d;
}
__device__ __forceinline__ ull pack2(float lo, float hi) {
    ull r; asm("mov.b64 %0, {%1, %2};" : "=l"(r) : "f"(lo), "f"(hi)); return r;
}
__device__ __forceinline__ float2 unpack2(ull v) {
    float2 r; asm("mov.b64 {%0, %1}, %2;" : "=f"(r.x), "=f"(r.y) : "l"(v)); return r;
}

/* ---------------- warp-mma helpers ---------------- */
__device__ __forceinline__ uint32_t smem_u32(const void* p) {
    uint32_t a;
    asm("{ .reg .u64 t; cvta.to.shared.u64 t, %1; cvt.u32.u64 %0, t; }" : "=r"(a) : "l"(p));
    return a;
}
__device__ __forceinline__ void mma16816(float* d, const uint32_t* a, const uint32_t* b) {
    asm("mma.sync.aligned.m16n8k16.row.col.f32.bf16.bf16.f32 "
        "{%0,%1,%2,%3}, {%4,%5,%6,%7}, {%8,%9}, {%0,%1,%2,%3};"
        : "+f"(d[0]), "+f"(d[1]), "+f"(d[2]), "+f"(d[3])
        : "r"(a[0]), "r"(a[1]), "r"(a[2]), "r"(a[3]), "r"(b[0]), "r"(b[1]));
}
__device__ __forceinline__ void ldsm4(uint32_t* r, uint32_t a) {
    asm volatile("ldmatrix.sync.aligned.m8n8.x4.shared.b16 {%0,%1,%2,%3}, [%4];"
                 : "=r"(r[0]), "=r"(r[1]), "=r"(r[2]), "=r"(r[3]) : "r"(a));
}
__device__ __forceinline__ void ldsm2(uint32_t* r, uint32_t a) {
    asm volatile("ldmatrix.sync.aligned.m8n8.x2.shared.b16 {%0,%1}, [%2];"
                 : "=r"(r[0]), "=r"(r[1]) : "r"(a));
}
__device__ __forceinline__ void ldsm2t(uint32_t* r, uint32_t a) {
    asm volatile("ldmatrix.sync.aligned.m8n8.x2.trans.shared.b16 {%0,%1}, [%2];"
                 : "=r"(r[0]), "=r"(r[1]) : "r"(a));
}
__device__ __forceinline__ void hilo(float v, __nv_bfloat16& h, __nv_bfloat16& l) {
    h = __float2bfloat16_rn(v);
    l = __float2bfloat16_rn(v - __bfloat162float(h));
}
__device__ __forceinline__ uint32_t packbf(__nv_bfloat16 a, __nv_bfloat16 b) {
    return (uint32_t)*(unsigned short*)&a | ((uint32_t)*(unsigned short*)&b << 16);
}

/* =============== projection GEMM (measured-good) =============== */
template<bool COMBINE>
__device__ __forceinline__ void gemm_body(const float* __restrict__ A,
                                          const float* __restrict__ B,
                                          float* __restrict__ C)
{
    __shared__ __align__(16) float As[2][16][68];
    __shared__ __align__(16) float Bs[2][16][68];
    const int t = threadIdx.x, tx = t & 15, ty = t >> 4;
    const int bi = blockIdx.y, bj = blockIdx.x;
    const int row = t >> 2, k4 = (t & 3) * 4;
    const int arow = bi * 64 + row;
    const float* Bg = B + (size_t)(bj * 64 + row) * 256 + k4;

    auto loadA = [&](int c0) -> float4 {
        if (COMBINE) {
            float4 n = *(const float4*)(g_pn + (size_t)arow * 256 + c0);
            float den = g_pd[arow * NHEAD + (c0 >> 5)];
#pragma unroll
            for (int s = 1; s < NSPL; s++) {
                float4 n2 = *(const float4*)(g_pn + (size_t)s * NTOK * 256 + (size_t)arow * 256 + c0);
                n.x += n2.x; n.y += n2.y; n.z += n2.z; n.w += n2.w;
                den += g_pd[s * NTOK * NHEAD + arow * NHEAD + (c0 >> 5)];
            }
            float inv = 1.0f / den;
            return make_float4(n.x * inv, n.y * inv, n.z * inv, n.w * inv);
        }
        return *(const float4*)(A + (size_t)arow * 256 + c0);
    };

    float4 av = loadA(k4), bv = *(const float4*)Bg;
    As[0][k4 + 0][row] = av.x; As[0][k4 + 1][row] = av.y; As[0][k4 + 2][row] = av.z; As[0][k4 + 3][row] = av.w;
    Bs[0][k4 + 0][row] = bv.x; Bs[0][k4 + 1][row] = bv.y; Bs[0][k4 + 2][row] = bv.z; Bs[0][k4 + 3][row] = bv.w;
    __syncthreads();
    ull acc2[4][2];
#pragma unroll
    for (int r = 0; r < 4; r++) { acc2[r][0] = 0ull; acc2[r][1] = 0ull; }
    for (int kt = 0; kt < 16; kt++) {
        const int cur = kt & 1;
        if (kt < 15) { av = loadA((kt + 1) * 16 + k4); bv = *(const float4*)(Bg + (kt + 1) * 16); }
#pragma unroll
        for (int kk = 0; kk < 16; kk++) {
            float4 a = *(const float4*)&As[cur][kk][ty * 4];
            ull b0 = *(const ull*)&Bs[cur][kk][tx * 4];
            ull b1 = *(const ull*)&Bs[cur][kk][tx * 4 + 2];
            ull a0 = pack2(a.x, a.x); acc2[0][0] = ffma2(a0, b0, acc2[0][0]); acc2[0][1] = ffma2(a0, b1, acc2[0][1]);
            ull a1 = pack2(a.y, a.y); acc2[1][0] = ffma2(a1, b0, acc2[1][0]); acc2[1][1] = ffma2(a1, b1, acc2[1][1]);
            ull a2 = pack2(a.z, a.z); acc2[2][0] = ffma2(a2, b0, acc2[2][0]); acc2[2][1] = ffma2(a2, b1, acc2[2][1]);
            ull a3 = pack2(a.w, a.w); acc2[3][0] = ffma2(a3, b0, acc2[3][0]); acc2[3][1] = ffma2(a3, b1, acc2[3][1]);
        }
        if (kt < 15) {
            const int nx = cur ^ 1;
            As[nx][k4 + 0][row] = av.x; As[nx][k4 + 1][row] = av.y; As[nx][k4 + 2][row] = av.z; As[nx][k4 + 3][row] = av.w;
            Bs[nx][k4 + 0][row] = bv.x; Bs[nx][k4 + 1][row] = bv.y; Bs[nx][k4 + 2][row] = bv.z; Bs[nx][k4 + 3][row] = bv.w;
        }
        __syncthreads();
    }
#pragma unroll
    for (int r = 0; r < 4; r++) {
        float2 lo = unpack2(acc2[r][0]), hi = unpack2(acc2[r][1]);
        *(float4*)(C + (size_t)(bi * 64 + ty * 4 + r) * 256 + bj * 64 + tx * 4) = make_float4(lo.x, lo.y, hi.x, hi.y);
    }
}

__global__ __launch_bounds__(256) void gemm_qkv(const float* __restrict__ x,
                                                const float* __restrict__ Wq,
                                                const float* __restrict__ Wk,
                                                const float* __restrict__ Wv)
{
    const float* B = (blockIdx.z == 0) ? Wq : (blockIdx.z == 1) ? Wk : Wv;
    float*       C = (blockIdx.z == 0) ? g_Q : (blockIdx.z == 1) ? g_K : g_V;
    gemm_body<false>(x, B, C);
}
__global__ __launch_bounds__(256) void gemm_out(const float* __restrict__ Wo, float* __restrict__ out)
{
    gemm_body<true>(nullptr, Wo, out);
}

/* =============== warp-mma attention =============== */
/* smem byte offsets within dynamic smem */
#define OFF_K   0
#define OFF_V   33792
#define OFF_W   67584         /* float Ws[8][32][33] */
#define OFF_PIT 101376        /* float pits[32][32]  */
#define SMEM_BYTES 105472

__global__ __launch_bounds__(256) void attn_mma(
    const float* __restrict__ pi, const float* __restrict__ tau,
    const float* __restrict__ adjs)
{
    extern __shared__ __align__(16) char smraw[];
    const uint32_t sb = smem_u32(smraw);
    __nv_bfloat16* Ksm = (__nv_bfloat16*)(smraw + OFF_K);   /* [2][32][264] */
    __nv_bfloat16* Vsm = (__nv_bfloat16*)(smraw + OFF_V);
    float* Ws   = (float*)(smraw + OFF_W);
    float* pits = (float*)(smraw + OFF_PIT);

    const int t = threadIdx.x, lane = t & 31, h = t >> 5;
    const int i0 = blockIdx.x * TIA;
    const int sy = blockIdx.y;
    const int jbase = sy * JR;
    const size_t NN = (size_t)NTOK * NTOK;

    /* pits[i][hm] = tau*pi */
    for (int idx = t; idx < TIA * 32; idx += 256) {
        int hm = idx & 31;
        pits[idx] = tau[hm >> 2] * pi[(size_t)(i0 + (idx >> 5)) * 32 + hm];
    }

    /* ---- stage Q (hi/lo) into K smem, pull A-fragments to registers ---- */
#pragma unroll
    for (int r = 0; r < 8; r++) {
        int idx = t + r * 256;           /* 2048 float4 units: 32 rows x 64 */
        int i = idx >> 6, c4 = idx & 63;
        float4 q = *(const float4*)(g_Q + (size_t)(i0 + i) * 256 + c4 * 4);
        __nv_bfloat16 h0, l0, h1, l1, h2, l2, h3, l3;
        hilo(q.x, h0, l0); hilo(q.y, h1, l1); hilo(q.z, h2, l2); hilo(q.w, h3, l3);
        ull hp = (ull)packbf(h0, h1) | ((ull)packbf(h2, h3) << 32);
        ull lp = (ull)packbf(l0, l1) | ((ull)packbf(l2, l3) << 32);
        *(ull*)(Ksm + (size_t)i * KSTR + c4 * 4) = hp;
        *(ull*)(Ksm + (size_t)KSTR * 32 + (size_t)i * KSTR + c4 * 4) = lp;
    }
    __syncthreads();
    uint32_t qh[2][2][4], ql[2][2][4];
#pragma unroll
    for (int it = 0; it < 2; it++)
#pragma unroll
        for (int ks = 0; ks < 2; ks++) {
            int row = it * 16 + (lane & 15);
            int col = 32 * h + ks * 16 + (lane >> 4) * 8;
            uint32_t a0 = sb + OFF_K + (row * KSTR + col) * 2;
            ldsm4(qh[it][ks], a0);
            ldsm4(ql[it][ks], a0 + 32 * KSTR * 2);
        }
    __syncthreads();

    float O[2][4][4];
#pragma unroll
    for (int it = 0; it < 2; it++)
#pragma unroll
        for (int n8 = 0; n8 < 4; n8++)
#pragma unroll
            for (int c = 0; c < 4; c++) O[it][n8][c] = 0.f;
    float rsum[4] = {0.f, 0.f, 0.f, 0.f};

    const int wi = t >> 3;          /* phase-A identity: i row */
    const int wj4 = (t & 7) * 4;    /* 4 j columns */

    for (int jt = 0; jt < NJT; jt++) {
        const int j0 = jbase + jt * TJA;

        /* ---- (a) K/V tile -> hi/lo bf16 smem ---- */
#pragma unroll
        for (int r = 0; r < 8; r++) {
            int idx = t + r * 256;
            int j = idx >> 6, c4 = idx & 63;
            float4 kq = *(const float4*)(g_K + (size_t)(j0 + j) * 256 + c4 * 4);
            float4 vq = *(const float4*)(g_V + (size_t)(j0 + j) * 256 + c4 * 4);
            __nv_bfloat16 h0, l0, h1, l1, h2, l2, h3, l3;
            hilo(kq.x, h0, l0); hilo(kq.y, h1, l1); hilo(kq.z, h2, l2); hilo(kq.w, h3, l3);
            *(ull*)(Ksm + (size_t)j * KSTR + c4 * 4) = (ull)packbf(h0, h1) | ((ull)packbf(h2, h3) << 32);
            *(ull*)(Ksm + (size_t)KSTR * 32 + (size_t)j * KSTR + c4 * 4) = (ull)packbf(l0, l1) | ((ull)packbf(l2, l3) << 32);
            hilo(vq.x, h0, l0); hilo(vq.y, h1, l1); hilo(vq.z, h2, l2); hilo(vq.w, h3, l3);
            *(ull*)(Vsm + (size_t)j * KSTR + c4 * 4) = (ull)packbf(h0, h1) | ((ull)packbf(h2, h3) << 32);
            *(ull*)(Vsm + (size_t)KSTR * 32 + (size_t)j * KSTR + c4 * 4) = (ull)packbf(l0, l1) | ((ull)packbf(l2, l3) << 32);
        }
        /* ---- (a2) graph weights: Ws[h][i][j] for this tile ---- */
        {
            const float* ab = adjs + (size_t)(i0 + wi) * NTOK + j0 + wj4;
            float4 a0 = *(const float4*)(ab);
            float4 a1 = *(const float4*)(ab + NN);
            float4 a2 = *(const float4*)(ab + 2 * NN);
            float4 a3 = *(const float4*)(ab + 3 * NN);
            const float* pp = pits + wi * 32;
#pragma unroll
            for (int hh = 0; hh < NHEAD; hh++) {
                float p0 = pp[hh * 4 + 0], p1 = pp[hh * 4 + 1], p2 = pp[hh * 4 + 2], p3 = pp[hh * 4 + 3];
                float* wd = Ws + (hh * 32 + wi) * 33 + wj4;
                wd[0] = fmaf(p3, a3.x, fmaf(p2, a2.x, fmaf(p1, a1.x, fmaf(p0, a0.x, EPSV))));
                wd[1] = fmaf(p3, a3.y, fmaf(p2, a2.y, fmaf(p1, a1.y, fmaf(p0, a0.y, EPSV))));
                wd[2] = fmaf(p3, a3.z, fmaf(p2, a2.z, fmaf(p1, a1.z, fmaf(p0, a0.z, EPSV))));
                wd[3] = fmaf(p3, a3.w, fmaf(p2, a2.w, fmaf(p1, a1.w, fmaf(p0, a0.w, EPSV))));
            }
        }
        __syncthreads();

        /* ---- (b) QK^T via HMMA, error-compensated ---- */
        float S[2][4][4];
#pragma unroll
        for (int it = 0; it < 2; it++)
#pragma unroll
            for (int j8 = 0; j8 < 4; j8++)
#pragma unroll
                for (int c = 0; c < 4; c++) S[it][j8][c] = 0.f;
#pragma unroll
        for (int j8 = 0; j8 < 4; j8++)
#pragma unroll
            for (int ks = 0; ks < 2; ks++) {
                int krow = j8 * 8 + (lane & 7);
                int kcol = 32 * h + ks * 16 + ((lane >> 3) & 1) * 8;
                uint32_t ad = sb + OFF_K + (krow * KSTR + kcol) * 2;
                uint32_t bh[2], bl[2];
                ldsm2(bh, ad);
                ldsm2(bl, ad + 32 * KSTR * 2);
#pragma unroll
                for (int it = 0; it < 2; it++) {
                    mma16816(S[it][j8], qh[it][ks], bh);
                    mma16816(S[it][j8], qh[it][ks], bl);
                    mma16816(S[it][j8], ql[it][ks], bh);
                }
            }

        /* ---- (c) p = w * exp(s*scale); repack D-frag -> A-frag (hi/lo) ---- */
        uint32_t ph[2][2][4], pl[2][2][4];
#pragma unroll
        for (int it = 0; it < 2; it++)
#pragma unroll
            for (int j8 = 0; j8 < 4; j8++) {
                int r0 = it * 16 + (lane >> 2);
                int c0 = j8 * 8 + 2 * (lane & 3);
                const float* wr0 = Ws + (h * 32 + r0) * 33 + c0;
                const float* wr1 = Ws + (h * 32 + r0 + 8) * 33 + c0;
                float p0 = wr0[0] * __expf(S[it][j8][0] * QKSCALE);
                float p1 = wr0[1] * __expf(S[it][j8][1] * QKSCALE);
                float p2 = wr1[0] * __expf(S[it][j8][2] * QKSCALE);
                float p3 = wr1[1] * __expf(S[it][j8][3] * QKSCALE);
                rsum[it * 2 + 0] += p0 + p1;
                rsum[it * 2 + 1] += p2 + p3;
                __nv_bfloat16 h0, l0, h1, l1, h2, l2, h3, l3;
                hilo(p0, h0, l0); hilo(p1, h1, l1); hilo(p2, h2, l2); hilo(p3, h3, l3);
                int kc = j8 >> 1, sl = (j8 & 1) * 2;
                ph[it][kc][sl + 0] = packbf(h0, h1);
                ph[it][kc][sl + 1] = packbf(h2, h3);
                pl[it][kc][sl + 0] = packbf(l0, l1);
                pl[it][kc][sl + 1] = packbf(l2, l3);
            }

        /* ---- (d) O += P @ V, error-compensated ---- */
#pragma unroll
        for (int n8 = 0; n8 < 4; n8++)
#pragma unroll
            for (int kc = 0; kc < 2; kc++) {
                int vrow = kc * 16 + (lane & 15);
                int vcol = 32 * h + n8 * 8;
                uint32_t ad = sb + OFF_V + (vrow * KSTR + vcol) * 2;
                uint32_t vh[2], vl[2];
                ldsm2t(vh, ad);
                ldsm2t(vl, ad + 32 * KSTR * 2);
#pragma unroll
                for (int it = 0; it < 2; it++) {
                    mma16816(O[it][n8], ph[it][kc], vh);
                    mma16816(O[it][n8], ph[it][kc], vl);
                    mma16816(O[it][n8], pl[it][kc], vh);
                }
            }
        __syncthreads();
    }

    /* ---- epilogue: row sums + partial stores ---- */
#pragma unroll
    for (int v = 0; v < 4; v++) {
        float x = rsum[v];
        x += __shfl_xor_sync(0xffffffffu, x, 1);
        x += __shfl_xor_sync(0xffffffffu, x, 2);
        rsum[v] = x;
    }
    if ((lane & 3) == 0) {
#pragma unroll
        for (int it = 0; it < 2; it++)
#pragma unroll
            for (int half = 0; half < 2; half++) {
                int row = it * 16 + (lane >> 2) + half * 8;
                g_pd[(size_t)sy * NTOK * NHEAD + (size_t)(i0 + row) * NHEAD + h] = rsum[it * 2 + half];
            }
    }
    float* pn = g_pn + (size_t)sy * NTOK * 256;
#pragma unroll
    for (int it = 0; it < 2; it++)
#pragma unroll
        for (int n8 = 0; n8 < 4; n8++) {
            int r0 = i0 + it * 16 + (lane >> 2);
            int c = 32 * h + n8 * 8 + 2 * (lane & 3);
            *(float2*)(pn + (size_t)r0 * 256 + c) = make_float2(O[it][n8][0], O[it][n8][1]);
            *(float2*)(pn + (size_t)(r0 + 8) * 256 + c) = make_float2(O[it][n8][2], O[it][n8][3]);
        }
}

/* ================================================================= */
extern "C" void kernel_launch(void* const* d_in, const int* in_sizes, int n_in,
                              void* d_out, int out_size)
{
    const float* x    = (const float*)d_in[0];
    const float* pi   = (const float*)d_in[1];
    const float* tau  = (const float*)d_in[2];
    const float* adjs = (const float*)d_in[3];
    const float* Wq   = (const float*)d_in[4];
    const float* Wk   = (const float*)d_in[5];
    const float* Wv   = (const float*)d_in[6];
    const float* Wo   = (const float*)d_in[7];
    float* out = (float*)d_out;

    cudaFuncSetAttribute(attn_mma, cudaFuncAttributeMaxDynamicSharedMemorySize, SMEM_BYTES);

    gemm_qkv<<<dim3(4, 32, 3), 256>>>(x, Wq, Wk, Wv);
    attn_mma<<<dim3(NTOK / TIA, NSPL), 256, SMEM_BYTES>>>(pi, tau, adjs);
    gemm_out<<<dim3(4, 32), 256>>>(Wo, out);
}